// round 1
// baseline (speedup 1.0000x reference)
#include <cuda_runtime.h>
#include <math.h>

// ---------------- problem constants ----------------
constexpr int B_  = 8;
constexpr int H_  = 28;
constexpr int W_  = 28;
constexpr int C_  = 1024;
constexpr int NH_ = 16;
constexpr int HD_ = 64;
constexpr int S_  = H_ * W_;        // 784
constexpr int M_  = B_ * S_;        // 6272 rows
constexpr int HID_ = 4096;
constexpr int BC_  = 512;
constexpr int G_   = B_ * NH_;      // 128 attention batches
constexpr float SCALE_ = 0.125f;    // 64^-0.5

// ---------------- workspace (__device__ globals; no allocation allowed) ---
__device__ float g_xn   [M_ * C_];          // 25.7 MB
__device__ float g_qkv  [M_ * 3 * C_];      // 77 MB
__device__ float g_q    [G_ * S_ * HD_];    // 25.7 MB
__device__ float g_kT   [G_ * HD_ * S_];    // 25.7 MB
__device__ float g_v    [G_ * S_ * HD_];    // 25.7 MB
__device__ float g_bh   [G_ * S_ * H_];     // 11.2 MB
__device__ float g_bw   [G_ * S_ * W_];     // 11.2 MB
__device__ float g_attn [(size_t)G_ * S_ * S_];  // 315 MB
__device__ float g_ao   [M_ * C_];          // attention out, [B,S,C]
__device__ float g_x1   [M_ * C_];
__device__ float g_mlp  [M_ * HID_];        // 103 MB
__device__ float g_x2   [M_ * C_];
__device__ float g_c1   [M_ * BC_];
__device__ float g_c1a  [M_ * BC_];
__device__ float g_c2   [M_ * BC_];
__device__ float g_c2a  [M_ * BC_];
__device__ float g_c3   [M_ * C_];

__device__ __forceinline__ float gelu_f(float x) {
    return 0.5f * x * (1.0f + erff(x * 0.7071067811865475f));
}

// ---------------- generic tiled SGEMM ----------------
// C[M,N] = alpha * A[M,K] @ B[K,N]  (+bias[n]) with epilogue:
//   EPI 0: plain   EPI 1: gelu   EPI 2: + res[gr*ldres+gc]
//   EPI 3: + bh[(g*M+gr)*28 + gc/28] + bw[(g*M+gr)*28 + gc%28]  (attn scores)
//   EPI 4: scatter to [B,S,C]: C[((g/16)*784+gr)*1024 + (g%16)*64 + gc]
template<int BM, int BN, int BK, int TM, int TN, int EPI>
__global__ void sgemm_k(const float* __restrict__ A, const float* __restrict__ Bm,
                        float* __restrict__ Cm,
                        int M, int N, int K, int lda, int ldb, int ldc,
                        long long sA, long long sB, long long sC,
                        const float* __restrict__ bias,
                        const float* __restrict__ res, int ldres,
                        float alpha,
                        const float* __restrict__ bh, const float* __restrict__ bw)
{
    constexpr int THREADS = (BM / TM) * (BN / TN);
    __shared__ float As[BK][BM];
    __shared__ float Bs[BK][BN];

    const int tid = threadIdx.x;
    const int bm = blockIdx.x * BM;
    const int bn = blockIdx.y * BN;
    const int g  = blockIdx.z;
    A  += (size_t)g * sA;
    Bm += (size_t)g * sB;
    if (EPI != 4) Cm += (size_t)g * sC;

    const int tc = (tid % (BN / TN)) * TN;
    const int tr = (tid / (BN / TN)) * TM;

    float acc[TM][TN];
    #pragma unroll
    for (int m = 0; m < TM; m++)
        #pragma unroll
        for (int n = 0; n < TN; n++) acc[m][n] = 0.f;

    for (int k0 = 0; k0 < K; k0 += BK) {
        for (int i = tid; i < BM * BK; i += THREADS) {
            int r = i / BK, c = i % BK;
            int gr = bm + r;
            As[c][r] = (gr < M) ? A[(size_t)gr * lda + (k0 + c)] : 0.f;
        }
        for (int i = tid; i < BK * BN; i += THREADS) {
            int r = i / BN, c = i % BN;
            int gc = bn + c;
            Bs[r][c] = (gc < N) ? Bm[(size_t)(k0 + r) * ldb + gc] : 0.f;
        }
        __syncthreads();
        #pragma unroll
        for (int kk = 0; kk < BK; kk++) {
            float av[TM], bv[TN];
            #pragma unroll
            for (int m = 0; m < TM; m++) av[m] = As[kk][tr + m];
            #pragma unroll
            for (int n = 0; n < TN; n++) bv[n] = Bs[kk][tc + n];
            #pragma unroll
            for (int m = 0; m < TM; m++)
                #pragma unroll
                for (int n = 0; n < TN; n++)
                    acc[m][n] = fmaf(av[m], bv[n], acc[m][n]);
        }
        __syncthreads();
    }

    #pragma unroll
    for (int m = 0; m < TM; m++) {
        int gr = bm + tr + m;
        if (gr >= M) continue;
        #pragma unroll
        for (int n = 0; n < TN; n++) {
            int gc = bn + tc + n;
            if (gc >= N) continue;
            float v = alpha * acc[m][n];
            if (bias) v += bias[gc];
            if (EPI == 1) v = gelu_f(v);
            else if (EPI == 2) v += res[(size_t)gr * ldres + gc];
            else if (EPI == 3) v += bh[((size_t)g * M + gr) * 28 + gc / 28]
                                  + bw[((size_t)g * M + gr) * 28 + gc % 28];
            if (EPI == 4)
                Cm[((size_t)(g >> 4) * 784 + gr) * 1024 + (g & 15) * 64 + gc] = v;
            else
                Cm[(size_t)gr * ldc + gc] = v;
        }
    }
}

// ---------------- 3x3 conv as implicit GEMM (512->512, pad 1) --------------
template<int BM, int BN, int BK, int TM, int TN>
__global__ void conv3x3_k(const float* __restrict__ In, const float* __restrict__ Wt,
                          float* __restrict__ Out)
{
    constexpr int THREADS = (BM / TM) * (BN / TN);
    constexpr int M = M_, N = BC_, K = 9 * BC_;   // 6272, 512, 4608
    __shared__ float As[BK][BM];
    __shared__ float Bs[BK][BN];

    const int tid = threadIdx.x;
    const int bm = blockIdx.x * BM;
    const int bn = blockIdx.y * BN;
    const int tc = (tid % (BN / TN)) * TN;
    const int tr = (tid / (BN / TN)) * TM;

    float acc[TM][TN];
    #pragma unroll
    for (int m = 0; m < TM; m++)
        #pragma unroll
        for (int n = 0; n < TN; n++) acc[m][n] = 0.f;

    for (int k0 = 0; k0 < K; k0 += BK) {
        for (int i = tid; i < BM * BK; i += THREADS) {
            int r = i / BK, c = i % BK;
            int gr = bm + r;
            int j  = k0 + c;
            int ky = j / (3 * BC_);
            int kx = (j / BC_) % 3;
            int ci = j & (BC_ - 1);
            int b  = gr / S_;
            int rem = gr - b * S_;
            int h  = rem / W_;
            int w  = rem - h * W_;
            int ih = h + ky - 1, iw = w + kx - 1;
            float val = 0.f;
            if (gr < M && (unsigned)ih < (unsigned)H_ && (unsigned)iw < (unsigned)W_)
                val = In[(((size_t)b * H_ + ih) * W_ + iw) * BC_ + ci];
            As[c][r] = val;
        }
        for (int i = tid; i < BK * BN; i += THREADS) {
            int r = i / BN, c = i % BN;
            Bs[r][c] = Wt[(size_t)(k0 + r) * BC_ + bn + c];
        }
        __syncthreads();
        #pragma unroll
        for (int kk = 0; kk < BK; kk++) {
            float av[TM], bv[TN];
            #pragma unroll
            for (int m = 0; m < TM; m++) av[m] = As[kk][tr + m];
            #pragma unroll
            for (int n = 0; n < TN; n++) bv[n] = Bs[kk][tc + n];
            #pragma unroll
            for (int m = 0; m < TM; m++)
                #pragma unroll
                for (int n = 0; n < TN; n++)
                    acc[m][n] = fmaf(av[m], bv[n], acc[m][n]);
        }
        __syncthreads();
    }

    #pragma unroll
    for (int m = 0; m < TM; m++) {
        int gr = bm + tr + m;
        if (gr >= M) continue;
        #pragma unroll
        for (int n = 0; n < TN; n++) {
            int gc = bn + tc + n;
            Out[(size_t)gr * BC_ + gc] = acc[m][n];
        }
    }
}

// ---------------- layernorm (+ optional gelu / residual) -------------------
// mode 0: out = LN(x)*w+b
// mode 1: out = gelu(LN(x)*w+b)
// mode 2: out = res + LN(x)*w+b
__global__ void ln_kernel(const float* __restrict__ x, const float* __restrict__ w,
                          const float* __restrict__ bp, float* __restrict__ out,
                          int Cw, float eps, int mode, const float* __restrict__ res)
{
    __shared__ float red1[32], red2[32];
    __shared__ float stats[2];
    const int row  = blockIdx.x;
    const int tid  = threadIdx.x;
    const int lane = tid & 31, wid = tid >> 5;
    const float* xr = x + (size_t)row * Cw;

    float s = 0.f, sq = 0.f;
    for (int i = tid; i < Cw; i += blockDim.x) { float t = xr[i]; s += t; sq += t * t; }
    #pragma unroll
    for (int o = 16; o; o >>= 1) {
        s  += __shfl_down_sync(0xffffffffu, s, o);
        sq += __shfl_down_sync(0xffffffffu, sq, o);
    }
    if (lane == 0) { red1[wid] = s; red2[wid] = sq; }
    __syncthreads();
    if (tid == 0) {
        float S = 0.f, Q = 0.f;
        int nw = blockDim.x >> 5;
        for (int i = 0; i < nw; i++) { S += red1[i]; Q += red2[i]; }
        float mean = S / Cw;
        float var  = Q / Cw - mean * mean;
        stats[0] = mean;
        stats[1] = rsqrtf(var + eps);
    }
    __syncthreads();
    const float mean = stats[0], rstd = stats[1];
    for (int i = tid; i < Cw; i += blockDim.x) {
        float y = (xr[i] - mean) * rstd * w[i] + bp[i];
        if (mode == 1) y = gelu_f(y);
        else if (mode == 2) y += res[(size_t)row * Cw + i];
        out[(size_t)row * Cw + i] = y;
    }
}

// ---------------- softmax over last axis (784) ------------------------------
__global__ void softmax_k(float* __restrict__ a, int Ncol)
{
    __shared__ float red[32];
    __shared__ float sval;
    const size_t row = blockIdx.x;
    float* p = a + row * (size_t)Ncol;
    const int tid = threadIdx.x, lane = tid & 31, wid = tid >> 5;

    float m = -1e30f;
    for (int i = tid; i < Ncol; i += blockDim.x) m = fmaxf(m, p[i]);
    #pragma unroll
    for (int o = 16; o; o >>= 1) m = fmaxf(m, __shfl_xor_sync(0xffffffffu, m, o));
    if (lane == 0) red[wid] = m;
    __syncthreads();
    if (tid == 0) {
        float mm = -1e30f;
        int nw = blockDim.x >> 5;
        for (int i = 0; i < nw; i++) mm = fmaxf(mm, red[i]);
        sval = mm;
    }
    __syncthreads();
    m = sval;
    __syncthreads();

    float s = 0.f;
    for (int i = tid; i < Ncol; i += blockDim.x) {
        float e = __expf(p[i] - m);
        p[i] = e;
        s += e;
    }
    #pragma unroll
    for (int o = 16; o; o >>= 1) s += __shfl_xor_sync(0xffffffffu, s, o);
    if (lane == 0) red[wid] = s;
    __syncthreads();
    if (tid == 0) {
        float ss = 0.f;
        int nw = blockDim.x >> 5;
        for (int i = 0; i < nw; i++) ss += red[i];
        sval = ss;
    }
    __syncthreads();
    const float inv = 1.f / sval;
    for (int i = tid; i < Ncol; i += blockDim.x) p[i] *= inv;
}

// ---------------- qkv repack: [B,S,3,NH,HD] -> q[G,S,HD], kT[G,HD,S], v[G,S,HD]
__global__ void repack_k(const float* __restrict__ qkv, float* __restrict__ q,
                         float* __restrict__ kT, float* __restrict__ v)
{
    int idx = blockIdx.x * blockDim.x + threadIdx.x;
    const int total = G_ * S_ * HD_;
    if (idx >= total) return;
    int d = idx & 63;
    int s = (idx >> 6) % S_;
    int g = idx / (64 * S_);
    int b = g >> 4, n = g & 15;
    size_t src = ((size_t)(b * S_ + s)) * (3 * C_) + n * 64 + d;
    q[idx] = qkv[src];
    v[idx] = qkv[src + 2 * C_];
    kT[((size_t)g * 64 + d) * S_ + s] = qkv[src + C_];
}

// ---------------- decomposed relative position bias -------------------------
// bh[g,s,k] = sum_d q[g,s,d] * rel_h[(h - k + 27)*64 + d],  h = s / 28
// bw[g,s,l] = sum_d q[g,s,d] * rel_w[(w - l + 27)*64 + d],  w = s % 28
__global__ void relbias_k(const float* __restrict__ q,
                          const float* __restrict__ rel_h,
                          const float* __restrict__ rel_w,
                          float* __restrict__ bh, float* __restrict__ bw)
{
    const int s = blockIdx.x % S_;
    const int g = blockIdx.x / S_;
    __shared__ float qs[64];
    const int t = threadIdx.x;     // 64 threads
    qs[t] = q[((size_t)g * S_ + s) * 64 + t];
    __syncthreads();
    const int h = s / W_, w = s % W_;
    if (t < 28) {
        const float* r = rel_h + (size_t)(h - t + 27) * 64;
        float acc = 0.f;
        #pragma unroll
        for (int d = 0; d < 64; d++) acc = fmaf(qs[d], r[d], acc);
        bh[((size_t)g * S_ + s) * 28 + t] = acc;
    } else if (t >= 32 && t < 60) {
        const int l = t - 32;
        const float* r = rel_w + (size_t)(w - l + 27) * 64;
        float acc = 0.f;
        #pragma unroll
        for (int d = 0; d < 64; d++) acc = fmaf(qs[d], r[d], acc);
        bw[((size_t)g * S_ + s) * 28 + l] = acc;
    }
}

// ---------------- launch ----------------------------------------------------
extern "C" void kernel_launch(void* const* d_in, const int* in_sizes, int n_in,
                              void* d_out, int out_size)
{
    const float* x       = (const float*)d_in[0];
    const float* norm1_w = (const float*)d_in[1];
    const float* norm1_b = (const float*)d_in[2];
    const float* qkv_w   = (const float*)d_in[3];
    const float* qkv_b   = (const float*)d_in[4];
    const float* proj_w  = (const float*)d_in[5];
    const float* proj_b  = (const float*)d_in[6];
    const float* rel_h   = (const float*)d_in[7];
    const float* rel_w   = (const float*)d_in[8];
    const float* norm2_w = (const float*)d_in[9];
    const float* norm2_b = (const float*)d_in[10];
    const float* fc1_w   = (const float*)d_in[11];
    const float* fc1_b   = (const float*)d_in[12];
    const float* fc2_w   = (const float*)d_in[13];
    const float* fc2_b   = (const float*)d_in[14];
    const float* conv1_w = (const float*)d_in[15];
    const float* ln1_w   = (const float*)d_in[16];
    const float* ln1_b   = (const float*)d_in[17];
    const float* conv2_w = (const float*)d_in[18];
    const float* ln2_w   = (const float*)d_in[19];
    const float* ln2_b   = (const float*)d_in[20];
    const float* conv3_w = (const float*)d_in[21];
    const float* ln3_w   = (const float*)d_in[22];
    const float* ln3_b   = (const float*)d_in[23];
    float* out = (float*)d_out;

    float *xn, *qkv, *q, *kT, *v, *bh, *bw, *attn, *ao, *x1, *mlp, *x2;
    float *c1, *c1a, *c2, *c2a, *c3;
    cudaGetSymbolAddress((void**)&xn,   g_xn);
    cudaGetSymbolAddress((void**)&qkv,  g_qkv);
    cudaGetSymbolAddress((void**)&q,    g_q);
    cudaGetSymbolAddress((void**)&kT,   g_kT);
    cudaGetSymbolAddress((void**)&v,    g_v);
    cudaGetSymbolAddress((void**)&bh,   g_bh);
    cudaGetSymbolAddress((void**)&bw,   g_bw);
    cudaGetSymbolAddress((void**)&attn, g_attn);
    cudaGetSymbolAddress((void**)&ao,   g_ao);
    cudaGetSymbolAddress((void**)&x1,   g_x1);
    cudaGetSymbolAddress((void**)&mlp,  g_mlp);
    cudaGetSymbolAddress((void**)&x2,   g_x2);
    cudaGetSymbolAddress((void**)&c1,   g_c1);
    cudaGetSymbolAddress((void**)&c1a,  g_c1a);
    cudaGetSymbolAddress((void**)&c2,   g_c2);
    cudaGetSymbolAddress((void**)&c2a,  g_c2a);
    cudaGetSymbolAddress((void**)&c3,   g_c3);

    // 1. LN1:  x -> xn
    ln_kernel<<<M_, 256>>>(x, norm1_w, norm1_b, xn, C_, 1e-5f, 0, nullptr);

    // 2. qkv GEMM: [6272,1024] @ [1024,3072] + bias -> qkv
    sgemm_k<128,128,8,8,8,0><<<dim3(M_/128, 3*C_/128, 1), 256>>>(
        xn, qkv_w, qkv, M_, 3*C_, C_, C_, 3*C_, 3*C_,
        0, 0, 0, qkv_b, nullptr, 0, 1.f, nullptr, nullptr);

    // 3. repack q / kT / v
    repack_k<<<(G_*S_*HD_ + 255)/256, 256>>>(qkv, q, kT, v);

    // 4. relative-position bias dots
    relbias_k<<<G_*S_, 64>>>(q, rel_h, rel_w, bh, bw);

    // 5. scores: attn = SCALE * q @ kT + bias_h + bias_w   (batched over 128)
    sgemm_k<128,128,8,8,8,3><<<dim3((S_+127)/128, (S_+127)/128, G_), 256>>>(
        q, kT, attn, S_, S_, HD_, HD_, S_, S_,
        (long long)S_*HD_, (long long)HD_*S_, (long long)S_*S_,
        nullptr, nullptr, 0, SCALE_, bh, bw);

    // 6. softmax rows
    softmax_k<<<G_*S_, 256>>>(attn, S_);

    // 7. AV: out[g] = attn[g] @ v[g], scattered into [B,S,C]
    sgemm_k<128,64,8,8,4,4><<<dim3((S_+127)/128, 1, G_), 256>>>(
        attn, v, ao, S_, HD_, S_, S_, HD_, 0,
        (long long)S_*S_, (long long)S_*HD_, 0,
        nullptr, nullptr, 0, 1.f, nullptr, nullptr);

    // 8. proj + residual: x1 = x + ao @ proj_w + proj_b
    sgemm_k<128,128,8,8,8,2><<<dim3(M_/128, C_/128, 1), 256>>>(
        ao, proj_w, x1, M_, C_, C_, C_, C_, C_,
        0, 0, 0, proj_b, x, C_, 1.f, nullptr, nullptr);

    // 9. LN2: x1 -> xn
    ln_kernel<<<M_, 256>>>(x1, norm2_w, norm2_b, xn, C_, 1e-5f, 0, nullptr);

    // 10. fc1 + gelu
    sgemm_k<128,128,8,8,8,1><<<dim3(M_/128, HID_/128, 1), 256>>>(
        xn, fc1_w, mlp, M_, HID_, C_, C_, HID_, HID_,
        0, 0, 0, fc1_b, nullptr, 0, 1.f, nullptr, nullptr);

    // 11. fc2 + residual: x2 = x1 + mlp @ fc2_w + fc2_b
    sgemm_k<128,128,8,8,8,2><<<dim3(M_/128, C_/128, 1), 256>>>(
        mlp, fc2_w, x2, M_, C_, HID_, HID_, C_, C_,
        0, 0, 0, fc2_b, x1, C_, 1.f, nullptr, nullptr);

    // 12. conv1 (1x1): c1 = x2 @ conv1_w
    sgemm_k<128,128,8,8,8,0><<<dim3(M_/128, BC_/128, 1), 256>>>(
        x2, conv1_w, c1, M_, BC_, C_, C_, BC_, BC_,
        0, 0, 0, nullptr, nullptr, 0, 1.f, nullptr, nullptr);

    // 13. LN(512, eps 1e-6) + gelu
    ln_kernel<<<M_, 256>>>(c1, ln1_w, ln1_b, c1a, BC_, 1e-6f, 1, nullptr);

    // 14. conv2 (3x3 implicit GEMM)
    conv3x3_k<128,128,8,8,8><<<dim3(M_/128, BC_/128, 1), 256>>>(c1a, conv2_w, c2);

    // 15. LN + gelu
    ln_kernel<<<M_, 256>>>(c2, ln2_w, ln2_b, c2a, BC_, 1e-6f, 1, nullptr);

    // 16. conv3 (1x1): c3 = c2a @ conv3_w
    sgemm_k<128,128,8,8,8,0><<<dim3(M_/128, C_/128, 1), 256>>>(
        c2a, conv3_w, c3, M_, C_, BC_, BC_, C_, C_,
        0, 0, 0, nullptr, nullptr, 0, 1.f, nullptr, nullptr);

    // 17. final: out = x2 + LN(c3)*ln3_w + ln3_b
    ln_kernel<<<M_, 256>>>(c3, ln3_w, ln3_b, out, C_, 1e-6f, 2, x2);
}